// round 12
// baseline (speedup 1.0000x reference)
#include <cuda_runtime.h>
#include <cuda_bf16.h>
#include <cstdint>

#define B_  32
#define C_  128
#define L_  256
#define CC_ (C_ * C_)      // 16384
#define BCC_ (B_ * CC_)    // 524288

// Scratch (device globals — no allocations allowed)
__device__ float    g_diff[BCC_];       // [b][i][j] pairwise L1
__device__ float    g_tmpS[BCC_];       // exp(relu((1-diffn)*a))
__device__ uint32_t g_Ah[4096 * 256];   // A=[x|y] bf16-hi packed x2, [row][kword]
__device__ uint32_t g_Al[4096 * 256];   // A bf16-lo residual
__device__ uint32_t g_Bh[256 * 256];    // B=(signed Theta^T) bf16-hi, [n][kword]
__device__ uint32_t g_Bl[256 * 256];    // B bf16-lo

// ===========================================================================
// helpers
// ===========================================================================
__device__ __forceinline__ void bf16_split2(float x, float y,
                                            uint32_t& hi, uint32_t& lo) {
    __nv_bfloat16 hx = __float2bfloat16(x);
    __nv_bfloat16 hy = __float2bfloat16(y);
    __nv_bfloat16 lx = __float2bfloat16(x - __bfloat162float(hx));
    __nv_bfloat16 ly = __float2bfloat16(y - __bfloat162float(hy));
    hi = (uint32_t)__bfloat16_as_ushort(hx) | ((uint32_t)__bfloat16_as_ushort(hy) << 16);
    lo = (uint32_t)__bfloat16_as_ushort(lx) | ((uint32_t)__bfloat16_as_ushort(ly) << 16);
}
__device__ __forceinline__ void mma_bf16(float c[4], const uint32_t a[4],
                                         const uint32_t b[2]) {
    asm volatile(
        "mma.sync.aligned.m16n8k16.row.col.f32.bf16.bf16.f32 "
        "{%0,%1,%2,%3}, {%4,%5,%6,%7}, {%8,%9}, {%0,%1,%2,%3};"
        : "+f"(c[0]), "+f"(c[1]), "+f"(c[2]), "+f"(c[3])
        : "r"(a[0]), "r"(a[1]), "r"(a[2]), "r"(a[3]), "r"(b[0]), "r"(b[1]));
}
__device__ __forceinline__ void ldmx4(uint32_t r[4], uint32_t addr) {
    asm volatile(
        "ldmatrix.sync.aligned.m8n8.x4.shared.b16 {%0,%1,%2,%3}, [%4];"
        : "=r"(r[0]), "=r"(r[1]), "=r"(r[2]), "=r"(r[3]) : "r"(addr));
}

// ---------------------------------------------------------------------------
// Kernel A (merged): bx<36: symmetric pairwise-L1 diff; 36..39: Theta ->
// bf16 hi/lo B operand; 40..43: x -> bf16 hi/lo A operand (k<256).
// grid (44, 32), 256 threads.
// ---------------------------------------------------------------------------
__global__ void __launch_bounds__(256) k_ttdiff(const float* __restrict__ x,
                                                const float* __restrict__ Theta) {
    __shared__ float sxi[16][260];
    __shared__ float sxj[16][260];
    const int tid = threadIdx.x;

    if (blockIdx.x >= 40) {
        // ---- x -> g_Ah/g_Al (words 0..127 of each row) ----
        const int id = (blockIdx.x - 40) * 32 + blockIdx.y;   // 0..127
#pragma unroll
        for (int it = 0; it < 8; it++) {
            int idx = id * 2048 + it * 256 + tid;             // 0..262143 float4s
            int row = idx >> 6, f4 = idx & 63;
            float4 v = *reinterpret_cast<const float4*>(x + (size_t)row * 256 + f4 * 4);
            uint32_t h0, l0v, h1, l1v;
            bf16_split2(v.x, v.y, h0, l0v);
            bf16_split2(v.z, v.w, h1, l1v);
            *reinterpret_cast<uint2*>(&g_Ah[(size_t)row * 256 + f4 * 2]) = make_uint2(h0, h1);
            *reinterpret_cast<uint2*>(&g_Al[(size_t)row * 256 + f4 * 2]) = make_uint2(l0v, l1v);
        }
        return;
    }

    if (blockIdx.x >= 36) {
        // ---- Theta transpose/sign-fold -> g_Bh/g_Bl ----
        __shared__ float t[32][33];
        const int id = (blockIdx.x - 36) * 32 + blockIdx.y;   // 0..127
        const int kt = (id >> 3) * 32, nt = (id & 7) * 32;
        const int tx = tid & 31, ty = tid >> 5;               // ty 0..7
#pragma unroll
        for (int r = 0; r < 32; r += 8) {
            int k = kt + ty + r;
            int n = nt + tx;
            float v = (k < 256) ? Theta[k * 256 + n]
                                : -Theta[65536 + (k - 256) * 256 + n];
            t[ty + r][tx] = v;                                 // t[k_local][n_local]
        }
        __syncthreads();
        const int nl = tid >> 3, wl8 = tid & 7;
#pragma unroll
        for (int rep = 0; rep < 2; rep++) {
            int wl = wl8 + rep * 8;                            // word 0..15
            uint32_t hv, lv;
            bf16_split2(t[2 * wl][nl], t[2 * wl + 1][nl], hv, lv);
            size_t o = (size_t)(nt + nl) * 256 + (kt >> 1) + wl;
            g_Bh[o] = hv;
            g_Bl[o] = lv;
        }
        return;
    }

    // ---- diff part: tile-pair (ti<=tj) of 16x16, mirror-write ----
    const int b = blockIdx.y;
    int rem = blockIdx.x, ti = 0;
    while (rem >= 8 - ti) { rem -= 8 - ti; ti++; }
    const int tj = ti + rem;
    const int i0 = ti * 16, j0 = tj * 16;
    const float* xb = x + b * C_ * L_;

#pragma unroll
    for (int rep = 0; rep < 4; rep++) {
        int idx = rep * 256 + tid;
        int row = idx >> 6, c4 = (idx & 63) * 4;
        *reinterpret_cast<float4*>(&sxi[row][c4]) =
            *reinterpret_cast<const float4*>(xb + (i0 + row) * L_ + c4);
        *reinterpret_cast<float4*>(&sxj[row][c4]) =
            *reinterpret_cast<const float4*>(xb + (j0 + row) * L_ + c4);
    }
    __syncthreads();

    const int ii = tid >> 4, jj = tid & 15;
    const float* ri = &sxi[ii][0];
    const float* rj = &sxj[jj][0];

    float a0 = 0.f, a1 = 0.f, a2 = 0.f, a3 = 0.f;
#pragma unroll
    for (int l = 0; l < L_; l += 16) {
        float4 u0 = *reinterpret_cast<const float4*>(ri + l);
        float4 v0 = *reinterpret_cast<const float4*>(rj + l);
        float4 u1 = *reinterpret_cast<const float4*>(ri + l + 4);
        float4 v1 = *reinterpret_cast<const float4*>(rj + l + 4);
        float4 u2 = *reinterpret_cast<const float4*>(ri + l + 8);
        float4 v2 = *reinterpret_cast<const float4*>(rj + l + 8);
        float4 u3 = *reinterpret_cast<const float4*>(ri + l + 12);
        float4 v3 = *reinterpret_cast<const float4*>(rj + l + 12);
        a0 += fabsf(u0.x - v0.x) + fabsf(u0.y - v0.y)
            + fabsf(u0.z - v0.z) + fabsf(u0.w - v0.w);
        a1 += fabsf(u1.x - v1.x) + fabsf(u1.y - v1.y)
            + fabsf(u1.z - v1.z) + fabsf(u1.w - v1.w);
        a2 += fabsf(u2.x - v2.x) + fabsf(u2.y - v2.y)
            + fabsf(u2.z - v2.z) + fabsf(u2.w - v2.w);
        a3 += fabsf(u3.x - v3.x) + fabsf(u3.y - v3.y)
            + fabsf(u3.z - v3.z) + fabsf(u3.w - v3.w);
    }
    float res = (a0 + a1) + (a2 + a3);

    g_diff[b * CC_ + (i0 + ii) * C_ + (j0 + jj)] = res;
    if (ti != tj)
        g_diff[b * CC_ + (j0 + jj) * C_ + (i0 + ii)] = res;
}

// ---------------------------------------------------------------------------
// Kernel B (fused norm+tmps): 2 threads per (i,j), b split 16/16, shfl combine.
// ---------------------------------------------------------------------------
__global__ void __launch_bounds__(128) k_nt(const float* __restrict__ a) {
    const int g  = blockIdx.x * 128 + threadIdx.x;
    const int ij = g >> 1;
    const int b0 = (g & 1) * 16;

    float d[16];
#pragma unroll
    for (int bb = 0; bb < 16; bb++) d[bb] = g_diff[(b0 + bb) * CC_ + ij];

    float ss = 0.f;
#pragma unroll
    for (int bb = 0; bb < 16; bb++) ss += d[bb] * d[bb];
    ss += __shfl_xor_sync(0xFFFFFFFFu, ss, 1);

    const float rn  = 1.f / fmaxf(sqrtf(ss), 1e-12f);
    const float aij = a[ij];

#pragma unroll
    for (int bb = 0; bb < 16; bb++) {
        float v = __expf(fmaxf((1.f - d[bb] * rn) * aij, 0.f));
        g_tmpS[(b0 + bb) * CC_ + ij] = v;
    }
}

// ---------------------------------------------------------------------------
// Kernel C: y[b,j,l] = (1/cs[b,j]) * sum_i tmpS[b,i,j] * x[b,i,l]
// Column sums in-kernel; epilogue writes bf16 hi/lo words into g_Ah/g_Al
// (words 128..255 of row b*128+j). grid (4 l, 4 j, 32 b), 128 threads.
// ---------------------------------------------------------------------------
__global__ void k_y(const float* __restrict__ x) {
    __shared__ float sS[16][32];
    __shared__ float sX[16][64];
    __shared__ float srcs[32];
    const int b  = blockIdx.z;
    const int j0 = blockIdx.y * 32;
    const int lBase = blockIdx.x * 64;
    const int tid = threadIdx.x;
    const int tx = tid & 15, ty = tid >> 4;  // ty 0..7

    float acc[4][4];
#pragma unroll
    for (int r = 0; r < 4; r++)
#pragma unroll
        for (int c = 0; c < 4; c++) acc[r][c] = 0.f;
    float csum = 0.f;

    const float* Sb = g_tmpS + b * CC_;
    const float* Xb = x + b * C_ * L_;

#pragma unroll 1
    for (int i0 = 0; i0 < C_; i0 += 16) {
        __syncthreads();
#pragma unroll
        for (int rep = 0; rep < 4; rep++) {
            int idx = rep * 128 + tid;
            int r = idx >> 5, c = idx & 31;
            sS[r][c] = Sb[(i0 + r) * C_ + j0 + c];
        }
#pragma unroll
        for (int rep = 0; rep < 8; rep++) {
            int idx = rep * 128 + tid;
            int r = idx >> 6, c = idx & 63;
            sX[r][c] = Xb[(i0 + r) * L_ + lBase + c];
        }
        __syncthreads();
        if (tid < 32) {
#pragma unroll
            for (int r = 0; r < 16; r++) csum += sS[r][tid];
        }
#pragma unroll
        for (int i = 0; i < 16; i++) {
            float4 av = *reinterpret_cast<const float4*>(&sS[i][ty * 4]);
            float4 bv = *reinterpret_cast<const float4*>(&sX[i][tx * 4]);
            float a4[4] = {av.x, av.y, av.z, av.w};
            float b4[4] = {bv.x, bv.y, bv.z, bv.w};
#pragma unroll
            for (int r = 0; r < 4; r++)
#pragma unroll
                for (int c = 0; c < 4; c++)
                    acc[r][c] += a4[r] * b4[c];
        }
    }
    if (tid < 32) srcs[tid] = 1.f / csum;
    __syncthreads();

#pragma unroll
    for (int r = 0; r < 4; r++) {
        int jj = j0 + ty * 4 + r;
        float rc = srcs[ty * 4 + r];
        float vx = acc[r][0] * rc, vy = acc[r][1] * rc;
        float vz = acc[r][2] * rc, vw = acc[r][3] * rc;
        uint32_t h0, l0v, h1, l1v;
        bf16_split2(vx, vy, h0, l0v);
        bf16_split2(vz, vw, h1, l1v);
        size_t o = (size_t)(b * 128 + jj) * 256 + 128 + (lBase >> 1) + tx * 2;
        *reinterpret_cast<uint2*>(&g_Ah[o]) = make_uint2(h0, h1);
        *reinterpret_cast<uint2*>(&g_Al[o]) = make_uint2(l0v, l1v);
    }
}

// ---------------------------------------------------------------------------
// Kernel D (bf16 m16n8k16 MMA, 3-product split, precomputed operands,
// ldmatrix, DOUBLE-BUFFERED single-sync pipeline, 8 warps):
//   out = relu(A @ B^T), M=4096, N=256, K=512.
// CTA 64x64, 256 threads (8 warps in 2m x 4n, warp tile 32x16).
// grid (4 n, 64 m) = 256 CTAs = 2048 warps. One __syncthreads per 32-k slab.
// ---------------------------------------------------------------------------
__global__ void __launch_bounds__(256) k_out_mma(float* __restrict__ out) {
    __shared__ uint32_t sAh[2][64][20], sAl[2][64][20];
    __shared__ uint32_t sBh[2][64][20], sBl[2][64][20];

    const int tid  = threadIdx.x;
    const int lane = tid & 31, wid = tid >> 5;   // 8 warps
    const int n0 = blockIdx.x * 64;
    const int r0 = blockIdx.y * 64;
    const int wm = (wid >> 2) * 32;   // 0 or 32
    const int wn = (wid & 3) * 16;    // 0,16,32,48
    const int qr = lane >> 2, qc = lane & 3;

    // ldmatrix per-lane addresses (bytes), buffer 0; buffer stride = 5120 B
    const int tq = lane >> 3, e = lane & 7;
    const uint32_t aoff = ((uint32_t)((wm + ((tq & 1) << 3) + e) * 20
                                      + ((tq >> 1) << 2))) << 2;
    const uint32_t boff = ((uint32_t)((wn + ((tq >> 1) << 3) + e) * 20
                                      + ((tq & 1) << 2))) << 2;
    const uint32_t adH0 = (uint32_t)__cvta_generic_to_shared(sAh) + aoff;
    const uint32_t adH1 = adH0 + 1280;                 // +16 rows
    const uint32_t adL0 = (uint32_t)__cvta_generic_to_shared(sAl) + aoff;
    const uint32_t adL1 = adL0 + 1280;
    const uint32_t bdH  = (uint32_t)__cvta_generic_to_shared(sBh) + boff;
    const uint32_t bdL  = (uint32_t)__cvta_generic_to_shared(sBl) + boff;

    // fill coords: 256 threads cover 64 rows x 16 words in one uint4 each
    const int frow = tid >> 2;              // 0..63
    const int fwq  = (tid & 3) * 4;         // word offset 0,4,8,12

    float acc[2][2][4];
#pragma unroll
    for (int mi = 0; mi < 2; mi++)
#pragma unroll
        for (int ni = 0; ni < 2; ni++)
#pragma unroll
            for (int ee = 0; ee < 4; ee++) acc[mi][ni][ee] = 0.f;

    uint4 pAh, pAl, pBh, pBl;
    {
        pAh = *reinterpret_cast<const uint4*>(&g_Ah[(size_t)(r0 + frow) * 256 + fwq]);
        pAl = *reinterpret_cast<const uint4*>(&g_Al[(size_t)(r0 + frow) * 256 + fwq]);
        pBh = *reinterpret_cast<const uint4*>(&g_Bh[(size_t)(n0 + frow) * 256 + fwq]);
        pBl = *reinterpret_cast<const uint4*>(&g_Bl[(size_t)(n0 + frow) * 256 + fwq]);
    }

#pragma unroll 1
    for (int s = 0; s < 16; s++) {
        const int buf = s & 1;
        // store current slab into its buffer (prev-prev reads completed
        // before the previous iteration's sync -> safe with one sync)
        *reinterpret_cast<uint4*>(&sAh[buf][frow][fwq]) = pAh;
        *reinterpret_cast<uint4*>(&sAl[buf][frow][fwq]) = pAl;
        *reinterpret_cast<uint4*>(&sBh[buf][frow][fwq]) = pBh;
        *reinterpret_cast<uint4*>(&sBl[buf][frow][fwq]) = pBl;
        __syncthreads();

        // prefetch next slab (overlaps MMA below)
        if (s < 15) {
            const int w0 = (s + 1) * 16 + fwq;
            pAh = *reinterpret_cast<const uint4*>(&g_Ah[(size_t)(r0 + frow) * 256 + w0]);
            pAl = *reinterpret_cast<const uint4*>(&g_Al[(size_t)(r0 + frow) * 256 + w0]);
            pBh = *reinterpret_cast<const uint4*>(&g_Bh[(size_t)(n0 + frow) * 256 + w0]);
            pBl = *reinterpret_cast<const uint4*>(&g_Bl[(size_t)(n0 + frow) * 256 + w0]);
        }

        const uint32_t bo = (uint32_t)buf * 5120u;
#pragma unroll
        for (int t16 = 0; t16 < 2; t16++) {
            const uint32_t o = bo + t16 * 32;   // 8 words per k16 step
            uint32_t AH0[4], AH1[4], AL0[4], AL1[4], BH[4], BL[4];
            ldmx4(AH0, adH0 + o);  ldmx4(AH1, adH1 + o);
            ldmx4(BH,  bdH  + o);  ldmx4(BL,  bdL  + o);
            ldmx4(AL0, adL0 + o);  ldmx4(AL1, adL1 + o);

            // pass 1: AH * BH
            mma_bf16(acc[0][0], AH0, &BH[0]);  mma_bf16(acc[0][1], AH0, &BH[2]);
            mma_bf16(acc[1][0], AH1, &BH[0]);  mma_bf16(acc[1][1], AH1, &BH[2]);
            // pass 2: AL * BH
            mma_bf16(acc[0][0], AL0, &BH[0]);  mma_bf16(acc[0][1], AL0, &BH[2]);
            mma_bf16(acc[1][0], AL1, &BH[0]);  mma_bf16(acc[1][1], AL1, &BH[2]);
            // pass 3: AH * BL
            mma_bf16(acc[0][0], AH0, &BL[0]);  mma_bf16(acc[0][1], AH0, &BL[2]);
            mma_bf16(acc[1][0], AH1, &BL[0]);  mma_bf16(acc[1][1], AH1, &BL[2]);
        }
    }

    // epilogue: relu + store
#pragma unroll
    for (int mi = 0; mi < 2; mi++) {
        int row = r0 + wm + mi * 16 + qr;
#pragma unroll
        for (int ni = 0; ni < 2; ni++) {
            int col = n0 + wn + ni * 8 + qc * 2;
            float2 v0 = make_float2(fmaxf(acc[mi][ni][0], 0.f),
                                    fmaxf(acc[mi][ni][1], 0.f));
            float2 v1 = make_float2(fmaxf(acc[mi][ni][2], 0.f),
                                    fmaxf(acc[mi][ni][3], 0.f));
            *reinterpret_cast<float2*>(out + (size_t)row * L_ + col) = v0;
            *reinterpret_cast<float2*>(out + (size_t)(row + 8) * L_ + col) = v1;
        }
    }
}

// ---------------------------------------------------------------------------
extern "C" void kernel_launch(void* const* d_in, const int* in_sizes, int n_in,
                              void* d_out, int out_size) {
    const float* x     = (const float*)d_in[0];   // [32,128,256]
    const float* a     = (const float*)d_in[1];   // [128,128]
    const float* Theta = (const float*)d_in[2];   // [2,256,256]
    float* out = (float*)d_out;                   // [32,128,256]

    k_ttdiff <<<dim3(44, 32),   256>>>(x, Theta);
    k_nt     <<<256,            128>>>(a);
    k_y      <<<dim3(4, 4, 32), 128>>>(x);
    k_out_mma<<<dim3(4, 64),    256>>>(out);
}

// round 13
// speedup vs baseline: 1.0746x; 1.0746x over previous
#include <cuda_runtime.h>
#include <cuda_bf16.h>
#include <cstdint>

#define B_  32
#define C_  128
#define L_  256
#define CC_ (C_ * C_)      // 16384
#define BCC_ (B_ * CC_)    // 524288

// Scratch (device globals — no allocations allowed)
__device__ float    g_diff[BCC_];       // [b][i][j] pairwise L1
__device__ float    g_tmpS[BCC_];       // exp(relu((1-diffn)*a))
__device__ uint32_t g_Ah[4096 * 256];   // A=[x|y] bf16-hi packed x2, [row][kword]
__device__ uint32_t g_Al[4096 * 256];   // A bf16-lo residual
__device__ uint32_t g_Bh[256 * 256];    // B=(signed Theta^T) bf16-hi, [n][kword]
__device__ uint32_t g_Bl[256 * 256];    // B bf16-lo

// ===========================================================================
// helpers
// ===========================================================================
__device__ __forceinline__ void bf16_split2(float x, float y,
                                            uint32_t& hi, uint32_t& lo) {
    __nv_bfloat16 hx = __float2bfloat16(x);
    __nv_bfloat16 hy = __float2bfloat16(y);
    __nv_bfloat16 lx = __float2bfloat16(x - __bfloat162float(hx));
    __nv_bfloat16 ly = __float2bfloat16(y - __bfloat162float(hy));
    hi = (uint32_t)__bfloat16_as_ushort(hx) | ((uint32_t)__bfloat16_as_ushort(hy) << 16);
    lo = (uint32_t)__bfloat16_as_ushort(lx) | ((uint32_t)__bfloat16_as_ushort(ly) << 16);
}
__device__ __forceinline__ void mma_bf16(float c[4], const uint32_t a[4],
                                         const uint32_t b[2]) {
    asm volatile(
        "mma.sync.aligned.m16n8k16.row.col.f32.bf16.bf16.f32 "
        "{%0,%1,%2,%3}, {%4,%5,%6,%7}, {%8,%9}, {%0,%1,%2,%3};"
        : "+f"(c[0]), "+f"(c[1]), "+f"(c[2]), "+f"(c[3])
        : "r"(a[0]), "r"(a[1]), "r"(a[2]), "r"(a[3]), "r"(b[0]), "r"(b[1]));
}
__device__ __forceinline__ void ldmx4(uint32_t r[4], uint32_t addr) {
    asm volatile(
        "ldmatrix.sync.aligned.m8n8.x4.shared.b16 {%0,%1,%2,%3}, [%4];"
        : "=r"(r[0]), "=r"(r[1]), "=r"(r[2]), "=r"(r[3]) : "r"(addr));
}
__device__ __forceinline__ void cpa16(uint32_t smem_addr, const void* gptr) {
    asm volatile("cp.async.ca.shared.global [%0], [%1], 16;"
                 :: "r"(smem_addr), "l"(gptr) : "memory");
}
__device__ __forceinline__ void cpa_commit() {
    asm volatile("cp.async.commit_group;" ::: "memory");
}
__device__ __forceinline__ void cpa_wait_all() {
    asm volatile("cp.async.wait_group 0;" ::: "memory");
}

// ---------------------------------------------------------------------------
// Kernel A (merged): bx<36: symmetric pairwise-L1 diff; 36..39: Theta ->
// bf16 hi/lo B operand; 40..43: x -> bf16 hi/lo A operand (k<256).
// grid (44, 32), 256 threads.
// ---------------------------------------------------------------------------
__global__ void __launch_bounds__(256) k_ttdiff(const float* __restrict__ x,
                                                const float* __restrict__ Theta) {
    __shared__ float sxi[16][260];
    __shared__ float sxj[16][260];
    const int tid = threadIdx.x;

    if (blockIdx.x >= 40) {
        // ---- x -> g_Ah/g_Al (words 0..127 of each row) ----
        const int id = (blockIdx.x - 40) * 32 + blockIdx.y;   // 0..127
#pragma unroll
        for (int it = 0; it < 8; it++) {
            int idx = id * 2048 + it * 256 + tid;             // 0..262143 float4s
            int row = idx >> 6, f4 = idx & 63;
            float4 v = *reinterpret_cast<const float4*>(x + (size_t)row * 256 + f4 * 4);
            uint32_t h0, l0v, h1, l1v;
            bf16_split2(v.x, v.y, h0, l0v);
            bf16_split2(v.z, v.w, h1, l1v);
            *reinterpret_cast<uint2*>(&g_Ah[(size_t)row * 256 + f4 * 2]) = make_uint2(h0, h1);
            *reinterpret_cast<uint2*>(&g_Al[(size_t)row * 256 + f4 * 2]) = make_uint2(l0v, l1v);
        }
        return;
    }

    if (blockIdx.x >= 36) {
        // ---- Theta transpose/sign-fold -> g_Bh/g_Bl ----
        __shared__ float t[32][33];
        const int id = (blockIdx.x - 36) * 32 + blockIdx.y;   // 0..127
        const int kt = (id >> 3) * 32, nt = (id & 7) * 32;
        const int tx = tid & 31, ty = tid >> 5;               // ty 0..7
#pragma unroll
        for (int r = 0; r < 32; r += 8) {
            int k = kt + ty + r;
            int n = nt + tx;
            float v = (k < 256) ? Theta[k * 256 + n]
                                : -Theta[65536 + (k - 256) * 256 + n];
            t[ty + r][tx] = v;                                 // t[k_local][n_local]
        }
        __syncthreads();
        const int nl = tid >> 3, wl8 = tid & 7;
#pragma unroll
        for (int rep = 0; rep < 2; rep++) {
            int wl = wl8 + rep * 8;                            // word 0..15
            uint32_t hv, lv;
            bf16_split2(t[2 * wl][nl], t[2 * wl + 1][nl], hv, lv);
            size_t o = (size_t)(nt + nl) * 256 + (kt >> 1) + wl;
            g_Bh[o] = hv;
            g_Bl[o] = lv;
        }
        return;
    }

    // ---- diff part: tile-pair (ti<=tj) of 16x16, mirror-write ----
    const int b = blockIdx.y;
    int rem = blockIdx.x, ti = 0;
    while (rem >= 8 - ti) { rem -= 8 - ti; ti++; }
    const int tj = ti + rem;
    const int i0 = ti * 16, j0 = tj * 16;
    const float* xb = x + b * C_ * L_;

#pragma unroll
    for (int rep = 0; rep < 4; rep++) {
        int idx = rep * 256 + tid;
        int row = idx >> 6, c4 = (idx & 63) * 4;
        *reinterpret_cast<float4*>(&sxi[row][c4]) =
            *reinterpret_cast<const float4*>(xb + (i0 + row) * L_ + c4);
        *reinterpret_cast<float4*>(&sxj[row][c4]) =
            *reinterpret_cast<const float4*>(xb + (j0 + row) * L_ + c4);
    }
    __syncthreads();

    const int ii = tid >> 4, jj = tid & 15;
    const float* ri = &sxi[ii][0];
    const float* rj = &sxj[jj][0];

    float a0 = 0.f, a1 = 0.f, a2 = 0.f, a3 = 0.f;
#pragma unroll
    for (int l = 0; l < L_; l += 16) {
        float4 u0 = *reinterpret_cast<const float4*>(ri + l);
        float4 v0 = *reinterpret_cast<const float4*>(rj + l);
        float4 u1 = *reinterpret_cast<const float4*>(ri + l + 4);
        float4 v1 = *reinterpret_cast<const float4*>(rj + l + 4);
        float4 u2 = *reinterpret_cast<const float4*>(ri + l + 8);
        float4 v2 = *reinterpret_cast<const float4*>(rj + l + 8);
        float4 u3 = *reinterpret_cast<const float4*>(ri + l + 12);
        float4 v3 = *reinterpret_cast<const float4*>(rj + l + 12);
        a0 += fabsf(u0.x - v0.x) + fabsf(u0.y - v0.y)
            + fabsf(u0.z - v0.z) + fabsf(u0.w - v0.w);
        a1 += fabsf(u1.x - v1.x) + fabsf(u1.y - v1.y)
            + fabsf(u1.z - v1.z) + fabsf(u1.w - v1.w);
        a2 += fabsf(u2.x - v2.x) + fabsf(u2.y - v2.y)
            + fabsf(u2.z - v2.z) + fabsf(u2.w - v2.w);
        a3 += fabsf(u3.x - v3.x) + fabsf(u3.y - v3.y)
            + fabsf(u3.z - v3.z) + fabsf(u3.w - v3.w);
    }
    float res = (a0 + a1) + (a2 + a3);

    g_diff[b * CC_ + (i0 + ii) * C_ + (j0 + jj)] = res;
    if (ti != tj)
        g_diff[b * CC_ + (j0 + jj) * C_ + (i0 + ii)] = res;
}

// ---------------------------------------------------------------------------
// Kernel B (fused norm+tmps): 2 threads per (i,j), b split 16/16, shfl combine.
// ---------------------------------------------------------------------------
__global__ void __launch_bounds__(128) k_nt(const float* __restrict__ a) {
    const int g  = blockIdx.x * 128 + threadIdx.x;
    const int ij = g >> 1;
    const int b0 = (g & 1) * 16;

    float d[16];
#pragma unroll
    for (int bb = 0; bb < 16; bb++) d[bb] = g_diff[(b0 + bb) * CC_ + ij];

    float ss = 0.f;
#pragma unroll
    for (int bb = 0; bb < 16; bb++) ss += d[bb] * d[bb];
    ss += __shfl_xor_sync(0xFFFFFFFFu, ss, 1);

    const float rn  = 1.f / fmaxf(sqrtf(ss), 1e-12f);
    const float aij = a[ij];

#pragma unroll
    for (int bb = 0; bb < 16; bb++) {
        float v = __expf(fmaxf((1.f - d[bb] * rn) * aij, 0.f));
        g_tmpS[(b0 + bb) * CC_ + ij] = v;
    }
}

// ---------------------------------------------------------------------------
// Kernel C: y[b,j,l] = (1/cs[b,j]) * sum_i tmpS[b,i,j] * x[b,i,l]
// Column sums in-kernel; epilogue writes bf16 hi/lo words into g_Ah/g_Al
// (words 128..255 of row b*128+j). grid (4 l, 4 j, 32 b), 128 threads.
// ---------------------------------------------------------------------------
__global__ void k_y(const float* __restrict__ x) {
    __shared__ float sS[16][32];
    __shared__ float sX[16][64];
    __shared__ float srcs[32];
    const int b  = blockIdx.z;
    const int j0 = blockIdx.y * 32;
    const int lBase = blockIdx.x * 64;
    const int tid = threadIdx.x;
    const int tx = tid & 15, ty = tid >> 4;  // ty 0..7

    float acc[4][4];
#pragma unroll
    for (int r = 0; r < 4; r++)
#pragma unroll
        for (int c = 0; c < 4; c++) acc[r][c] = 0.f;
    float csum = 0.f;

    const float* Sb = g_tmpS + b * CC_;
    const float* Xb = x + b * C_ * L_;

#pragma unroll 1
    for (int i0 = 0; i0 < C_; i0 += 16) {
        __syncthreads();
#pragma unroll
        for (int rep = 0; rep < 4; rep++) {
            int idx = rep * 128 + tid;
            int r = idx >> 5, c = idx & 31;
            sS[r][c] = Sb[(i0 + r) * C_ + j0 + c];
        }
#pragma unroll
        for (int rep = 0; rep < 8; rep++) {
            int idx = rep * 128 + tid;
            int r = idx >> 6, c = idx & 63;
            sX[r][c] = Xb[(i0 + r) * L_ + lBase + c];
        }
        __syncthreads();
        if (tid < 32) {
#pragma unroll
            for (int r = 0; r < 16; r++) csum += sS[r][tid];
        }
#pragma unroll
        for (int i = 0; i < 16; i++) {
            float4 av = *reinterpret_cast<const float4*>(&sS[i][ty * 4]);
            float4 bv = *reinterpret_cast<const float4*>(&sX[i][tx * 4]);
            float a4[4] = {av.x, av.y, av.z, av.w};
            float b4[4] = {bv.x, bv.y, bv.z, bv.w};
#pragma unroll
            for (int r = 0; r < 4; r++)
#pragma unroll
                for (int c = 0; c < 4; c++)
                    acc[r][c] += a4[r] * b4[c];
        }
    }
    if (tid < 32) srcs[tid] = 1.f / csum;
    __syncthreads();

#pragma unroll
    for (int r = 0; r < 4; r++) {
        int jj = j0 + ty * 4 + r;
        float rc = srcs[ty * 4 + r];
        float vx = acc[r][0] * rc, vy = acc[r][1] * rc;
        float vz = acc[r][2] * rc, vw = acc[r][3] * rc;
        uint32_t h0, l0v, h1, l1v;
        bf16_split2(vx, vy, h0, l0v);
        bf16_split2(vz, vw, h1, l1v);
        size_t o = (size_t)(b * 128 + jj) * 256 + 128 + (lBase >> 1) + tx * 2;
        *reinterpret_cast<uint2*>(&g_Ah[o]) = make_uint2(h0, h1);
        *reinterpret_cast<uint2*>(&g_Al[o]) = make_uint2(l0v, l1v);
    }
}

// ---------------------------------------------------------------------------
// Kernel D (bf16 m16n8k16 MMA, 3-product split, precomputed operands,
// ldmatrix, cp.async 2-stage smem pipeline):
//   out = relu(A @ B^T), M=4096, N=256, K=512.
// CTA 64x64, 128 threads (4 warps 2x2, warp tile 32x32). grid (4 n, 64 m).
// Per slab: 8 LDGSTS/thread, 1 wait + 1 sync, 16 ldmx4 + 48 MMA per warp.
// smem: 2 stages x 4 arrays x 64 rows x 20 words = 40 KB static.
// ---------------------------------------------------------------------------
#define STG_W   (64 * 20)          // words per array
#define STG_B   (STG_W * 4)        // 5120 bytes per array
#define STAGE_B (4 * STG_B)        // 20480 bytes per stage

__global__ void __launch_bounds__(128) k_out_mma(float* __restrict__ out) {
    __shared__ uint32_t sm[2][4][64][20];   // [stage][Ah,Al,Bh,Bl][row][word]

    const int tid  = threadIdx.x;
    const int lane = tid & 31, wid = tid >> 5;
    const int n0 = blockIdx.x * 64;
    const int r0 = blockIdx.y * 64;
    const int wm = (wid >> 1) * 32;
    const int wn = (wid & 1) * 32;
    const int qr = lane >> 2, qc = lane & 3;

    const uint32_t smbase = (uint32_t)__cvta_generic_to_shared(sm);

    // ldmatrix per-lane offsets (bytes within a stage)
    const int tq = lane >> 3, e = lane & 7;
    const uint32_t aoff = ((uint32_t)((wm + ((tq & 1) << 3) + e) * 20
                                      + ((tq >> 1) << 2))) << 2;
    const uint32_t boff = ((uint32_t)((wn + ((tq >> 1) << 3) + e) * 20
                                      + ((tq & 1) << 2))) << 2;
    const uint32_t adH0 = smbase + 0 * STG_B + aoff;
    const uint32_t adH1 = adH0 + 1280;                 // +16 rows
    const uint32_t adL0 = smbase + 1 * STG_B + aoff;
    const uint32_t adL1 = adL0 + 1280;
    const uint32_t bdH0 = smbase + 2 * STG_B + boff;
    const uint32_t bdH1 = bdH0 + 1280;
    const uint32_t bdL0 = smbase + 3 * STG_B + boff;
    const uint32_t bdL1 = bdL0 + 1280;

    // fill coords: 128 threads x 2 reps cover 64 rows x 16 words per array
    const int frow = tid >> 2;              // 0..31 (rep adds 32)
    const int fwq  = (tid & 3) * 4;         // word offset 0,4,8,12
    const uint32_t foff0 = smbase + (uint32_t)((frow * 20 + fwq) << 2);
    const uint32_t foff1 = smbase + (uint32_t)(((frow + 32) * 20 + fwq) << 2);

    float acc[2][4][4];
#pragma unroll
    for (int mi = 0; mi < 2; mi++)
#pragma unroll
        for (int ni = 0; ni < 4; ni++)
#pragma unroll
            for (int ee = 0; ee < 4; ee++) acc[mi][ni][ee] = 0.f;

    // issue slab 0 into stage 0
    {
        const int w0 = fwq;
        cpa16(foff0 + 0 * STG_B, &g_Ah[(size_t)(r0 + frow) * 256 + w0]);
        cpa16(foff1 + 0 * STG_B, &g_Ah[(size_t)(r0 + frow + 32) * 256 + w0]);
        cpa16(foff0 + 1 * STG_B, &g_Al[(size_t)(r0 + frow) * 256 + w0]);
        cpa16(foff1 + 1 * STG_B, &g_Al[(size_t)(r0 + frow + 32) * 256 + w0]);
        cpa16(foff0 + 2 * STG_B, &g_Bh[(size_t)(n0 + frow) * 256 + w0]);
        cpa16(foff1 + 2 * STG_B, &g_Bh[(size_t)(n0 + frow + 32) * 256 + w0]);
        cpa16(foff0 + 3 * STG_B, &g_Bl[(size_t)(n0 + frow) * 256 + w0]);
        cpa16(foff1 + 3 * STG_B, &g_Bl[(size_t)(n0 + frow + 32) * 256 + w0]);
        cpa_commit();
    }

#pragma unroll 1
    for (int s = 0; s < 16; s++) {
        cpa_wait_all();
        __syncthreads();   // slab s visible to all; stage (s+1)&1 fully consumed

        // issue slab s+1 into the other stage (overlaps MMA below)
        if (s < 15) {
            const uint32_t sb = (uint32_t)((s + 1) & 1) * STAGE_B;
            const int w0 = (s + 1) * 16 + fwq;
            cpa16(sb + foff0 + 0 * STG_B, &g_Ah[(size_t)(r0 + frow) * 256 + w0]);
            cpa16(sb + foff1 + 0 * STG_B, &g_Ah[(size_t)(r0 + frow + 32) * 256 + w0]);
            cpa16(sb + foff0 + 1 * STG_B, &g_Al[(size_t)(r0 + frow) * 256 + w0]);
            cpa16(sb + foff1 + 1 * STG_B, &g_Al[(size_t)(r0 + frow + 32) * 256 + w0]);
            cpa16(sb + foff0 + 2 * STG_B, &g_Bh[(size_t)(n0 + frow) * 256 + w0]);
            cpa16(sb + foff1 + 2 * STG_B, &g_Bh[(size_t)(n0 + frow + 32) * 256 + w0]);
            cpa16(sb + foff0 + 3 * STG_B, &g_Bl[(size_t)(n0 + frow) * 256 + w0]);
            cpa16(sb + foff1 + 3 * STG_B, &g_Bl[(size_t)(n0 + frow + 32) * 256 + w0]);
            cpa_commit();
        }

        const uint32_t so = (uint32_t)(s & 1) * STAGE_B;
#pragma unroll
        for (int t16 = 0; t16 < 2; t16++) {
            const uint32_t o = so + t16 * 32;   // 8 words per k16 step
            uint32_t AH0[4], AH1[4], AL0[4], AL1[4];
            uint32_t BH0[4], BH1[4], BL0[4], BL1[4];
            ldmx4(AH0, adH0 + o);  ldmx4(AH1, adH1 + o);
            ldmx4(BH0, bdH0 + o);  ldmx4(BH1, bdH1 + o);
            ldmx4(AL0, adL0 + o);  ldmx4(AL1, adL1 + o);
            ldmx4(BL0, bdL0 + o);  ldmx4(BL1, bdL1 + o);

            // pass 1: AH * BH
            mma_bf16(acc[0][0], AH0, &BH0[0]);  mma_bf16(acc[0][1], AH0, &BH0[2]);
            mma_bf16(acc[0][2], AH0, &BH1[0]);  mma_bf16(acc[0][3], AH0, &BH1[2]);
            mma_bf16(acc[1][0], AH1, &BH0[0]);  mma_bf16(acc[1][1], AH1, &BH0[2]);
            mma_bf16(acc[1][2], AH1, &BH1[0]);  mma_bf16(acc[1][3], AH1, &BH1[2]);
            // pass 2: AL * BH
            mma_bf16(acc[0][0], AL0, &BH0[0]);  mma_bf16(acc[0][1], AL0, &BH0[2]);
            mma_bf16(acc[0][2], AL0, &BH1[0]);  mma_bf16(acc[0][3], AL0, &BH1[2]);
            mma_bf16(acc[1][0], AL1, &BH0[0]);  mma_bf16(acc[1][1], AL1, &BH0[2]);
            mma_bf16(acc[1][2], AL1, &BH1[0]);  mma_bf16(acc[1][3], AL1, &BH1[2]);
            // pass 3: AH * BL
            mma_bf16(acc[0][0], AH0, &BL0[0]);  mma_bf16(acc[0][1], AH0, &BL0[2]);
            mma_bf16(acc[0][2], AH0, &BL1[0]);  mma_bf16(acc[0][3], AH0, &BL1[2]);
            mma_bf16(acc[1][0], AH1, &BL0[0]);  mma_bf16(acc[1][1], AH1, &BL0[2]);
            mma_bf16(acc[1][2], AH1, &BL1[0]);  mma_bf16(acc[1][3], AH1, &BL1[2]);
        }
    }

    // epilogue: relu + store
#pragma unroll
    for (int mi = 0; mi < 2; mi++) {
        int row = r0 + wm + mi * 16 + qr;
#pragma unroll
        for (int ni = 0; ni < 4; ni++) {
            int col = n0 + wn + ni * 8 + qc * 2;
            float2 v0 = make_float2(fmaxf(acc[mi][ni][0], 0.f),
                                    fmaxf(acc[mi][ni][1], 0.f));
            float2 v1 = make_float2(fmaxf(acc[mi][ni][2], 0.f),
                                    fmaxf(acc[mi][ni][3], 0.f));
            *reinterpret_cast<float2*>(out + (size_t)row * L_ + col) = v0;
            *reinterpret_cast<float2*>(out + (size_t)(row + 8) * L_ + col) = v1;
        }
    }
}

// ---------------------------------------------------------------------------
extern "C" void kernel_launch(void* const* d_in, const int* in_sizes, int n_in,
                              void* d_out, int out_size) {
    const float* x     = (const float*)d_in[0];   // [32,128,256]
    const float* a     = (const float*)d_in[1];   // [128,128]
    const float* Theta = (const float*)d_in[2];   // [2,256,256]
    float* out = (float*)d_out;                   // [32,128,256]

    k_ttdiff <<<dim3(44, 32),   256>>>(x, Theta);
    k_nt     <<<256,            128>>>(a);
    k_y      <<<dim3(4, 4, 32), 128>>>(x);
    k_out_mma<<<dim3(4, 64),    128>>>(out);
}

// round 14
// speedup vs baseline: 1.0766x; 1.0019x over previous
#include <cuda_runtime.h>
#include <cuda_bf16.h>
#include <cstdint>

#define B_  32
#define C_  128
#define L_  256
#define CC_ (C_ * C_)      // 16384
#define BCC_ (B_ * CC_)    // 524288

// Scratch (device globals — no allocations allowed)
__device__ float    g_diff[BCC_];       // [b][i][j] pairwise L1
__device__ float    g_tmpS[BCC_];       // exp(relu((1-diffn)*a))
__device__ uint32_t g_Ah[4096 * 256];   // A=[x|y] bf16-hi packed x2, [row][kword]
__device__ uint32_t g_Al[4096 * 256];   // A bf16-lo residual
__device__ uint32_t g_Bh[256 * 256];    // B=(signed Theta^T) bf16-hi, [n][kword]
__device__ uint32_t g_Bl[256 * 256];    // B bf16-lo

// ===========================================================================
// helpers
// ===========================================================================
__device__ __forceinline__ void bf16_split2(float x, float y,
                                            uint32_t& hi, uint32_t& lo) {
    __nv_bfloat16 hx = __float2bfloat16(x);
    __nv_bfloat16 hy = __float2bfloat16(y);
    __nv_bfloat16 lx = __float2bfloat16(x - __bfloat162float(hx));
    __nv_bfloat16 ly = __float2bfloat16(y - __bfloat162float(hy));
    hi = (uint32_t)__bfloat16_as_ushort(hx) | ((uint32_t)__bfloat16_as_ushort(hy) << 16);
    lo = (uint32_t)__bfloat16_as_ushort(lx) | ((uint32_t)__bfloat16_as_ushort(ly) << 16);
}
__device__ __forceinline__ void mma_bf16(float c[4], const uint32_t a[4],
                                         const uint32_t b[2]) {
    asm volatile(
        "mma.sync.aligned.m16n8k16.row.col.f32.bf16.bf16.f32 "
        "{%0,%1,%2,%3}, {%4,%5,%6,%7}, {%8,%9}, {%0,%1,%2,%3};"
        : "+f"(c[0]), "+f"(c[1]), "+f"(c[2]), "+f"(c[3])
        : "r"(a[0]), "r"(a[1]), "r"(a[2]), "r"(a[3]), "r"(b[0]), "r"(b[1]));
}
__device__ __forceinline__ void ldmx4(uint32_t r[4], uint32_t addr) {
    asm volatile(
        "ldmatrix.sync.aligned.m8n8.x4.shared.b16 {%0,%1,%2,%3}, [%4];"
        : "=r"(r[0]), "=r"(r[1]), "=r"(r[2]), "=r"(r[3]) : "r"(addr));
}
__device__ __forceinline__ void cpa16(uint32_t smem_addr, const void* gptr) {
    asm volatile("cp.async.ca.shared.global [%0], [%1], 16;"
                 :: "r"(smem_addr), "l"(gptr) : "memory");
}
__device__ __forceinline__ void cpa_commit() {
    asm volatile("cp.async.commit_group;" ::: "memory");
}
__device__ __forceinline__ void cpa_wait1() {
    asm volatile("cp.async.wait_group 1;" ::: "memory");
}
__device__ __forceinline__ void cpa_wait0() {
    asm volatile("cp.async.wait_group 0;" ::: "memory");
}

// ---------------------------------------------------------------------------
// Kernel A (merged): bx<36: symmetric pairwise-L1 diff; 36..39: Theta ->
// bf16 hi/lo B operand; 40..43: x -> bf16 hi/lo A operand (k<256).
// grid (44, 32), 256 threads.
// ---------------------------------------------------------------------------
__global__ void __launch_bounds__(256) k_ttdiff(const float* __restrict__ x,
                                                const float* __restrict__ Theta) {
    __shared__ float sxi[16][260];
    __shared__ float sxj[16][260];
    const int tid = threadIdx.x;

    if (blockIdx.x >= 40) {
        // ---- x -> g_Ah/g_Al (words 0..127 of each row) ----
        const int id = (blockIdx.x - 40) * 32 + blockIdx.y;   // 0..127
#pragma unroll
        for (int it = 0; it < 8; it++) {
            int idx = id * 2048 + it * 256 + tid;             // 0..262143 float4s
            int row = idx >> 6, f4 = idx & 63;
            float4 v = *reinterpret_cast<const float4*>(x + (size_t)row * 256 + f4 * 4);
            uint32_t h0, l0v, h1, l1v;
            bf16_split2(v.x, v.y, h0, l0v);
            bf16_split2(v.z, v.w, h1, l1v);
            *reinterpret_cast<uint2*>(&g_Ah[(size_t)row * 256 + f4 * 2]) = make_uint2(h0, h1);
            *reinterpret_cast<uint2*>(&g_Al[(size_t)row * 256 + f4 * 2]) = make_uint2(l0v, l1v);
        }
        return;
    }

    if (blockIdx.x >= 36) {
        // ---- Theta transpose/sign-fold -> g_Bh/g_Bl ----
        __shared__ float t[32][33];
        const int id = (blockIdx.x - 36) * 32 + blockIdx.y;   // 0..127
        const int kt = (id >> 3) * 32, nt = (id & 7) * 32;
        const int tx = tid & 31, ty = tid >> 5;               // ty 0..7
#pragma unroll
        for (int r = 0; r < 32; r += 8) {
            int k = kt + ty + r;
            int n = nt + tx;
            float v = (k < 256) ? Theta[k * 256 + n]
                                : -Theta[65536 + (k - 256) * 256 + n];
            t[ty + r][tx] = v;                                 // t[k_local][n_local]
        }
        __syncthreads();
        const int nl = tid >> 3, wl8 = tid & 7;
#pragma unroll
        for (int rep = 0; rep < 2; rep++) {
            int wl = wl8 + rep * 8;                            // word 0..15
            uint32_t hv, lv;
            bf16_split2(t[2 * wl][nl], t[2 * wl + 1][nl], hv, lv);
            size_t o = (size_t)(nt + nl) * 256 + (kt >> 1) + wl;
            g_Bh[o] = hv;
            g_Bl[o] = lv;
        }
        return;
    }

    // ---- diff part: tile-pair (ti<=tj) of 16x16, mirror-write ----
    const int b = blockIdx.y;
    int rem = blockIdx.x, ti = 0;
    while (rem >= 8 - ti) { rem -= 8 - ti; ti++; }
    const int tj = ti + rem;
    const int i0 = ti * 16, j0 = tj * 16;
    const float* xb = x + b * C_ * L_;

#pragma unroll
    for (int rep = 0; rep < 4; rep++) {
        int idx = rep * 256 + tid;
        int row = idx >> 6, c4 = (idx & 63) * 4;
        *reinterpret_cast<float4*>(&sxi[row][c4]) =
            *reinterpret_cast<const float4*>(xb + (i0 + row) * L_ + c4);
        *reinterpret_cast<float4*>(&sxj[row][c4]) =
            *reinterpret_cast<const float4*>(xb + (j0 + row) * L_ + c4);
    }
    __syncthreads();

    const int ii = tid >> 4, jj = tid & 15;
    const float* ri = &sxi[ii][0];
    const float* rj = &sxj[jj][0];

    float a0 = 0.f, a1 = 0.f, a2 = 0.f, a3 = 0.f;
#pragma unroll
    for (int l = 0; l < L_; l += 16) {
        float4 u0 = *reinterpret_cast<const float4*>(ri + l);
        float4 v0 = *reinterpret_cast<const float4*>(rj + l);
        float4 u1 = *reinterpret_cast<const float4*>(ri + l + 4);
        float4 v1 = *reinterpret_cast<const float4*>(rj + l + 4);
        float4 u2 = *reinterpret_cast<const float4*>(ri + l + 8);
        float4 v2 = *reinterpret_cast<const float4*>(rj + l + 8);
        float4 u3 = *reinterpret_cast<const float4*>(ri + l + 12);
        float4 v3 = *reinterpret_cast<const float4*>(rj + l + 12);
        a0 += fabsf(u0.x - v0.x) + fabsf(u0.y - v0.y)
            + fabsf(u0.z - v0.z) + fabsf(u0.w - v0.w);
        a1 += fabsf(u1.x - v1.x) + fabsf(u1.y - v1.y)
            + fabsf(u1.z - v1.z) + fabsf(u1.w - v1.w);
        a2 += fabsf(u2.x - v2.x) + fabsf(u2.y - v2.y)
            + fabsf(u2.z - v2.z) + fabsf(u2.w - v2.w);
        a3 += fabsf(u3.x - v3.x) + fabsf(u3.y - v3.y)
            + fabsf(u3.z - v3.z) + fabsf(u3.w - v3.w);
    }
    float res = (a0 + a1) + (a2 + a3);

    g_diff[b * CC_ + (i0 + ii) * C_ + (j0 + jj)] = res;
    if (ti != tj)
        g_diff[b * CC_ + (j0 + jj) * C_ + (i0 + ii)] = res;
}

// ---------------------------------------------------------------------------
// Kernel B (fused norm+tmps): 2 threads per (i,j), b split 16/16, shfl combine.
// ---------------------------------------------------------------------------
__global__ void __launch_bounds__(128) k_nt(const float* __restrict__ a) {
    const int g  = blockIdx.x * 128 + threadIdx.x;
    const int ij = g >> 1;
    const int b0 = (g & 1) * 16;

    float d[16];
#pragma unroll
    for (int bb = 0; bb < 16; bb++) d[bb] = g_diff[(b0 + bb) * CC_ + ij];

    float ss = 0.f;
#pragma unroll
    for (int bb = 0; bb < 16; bb++) ss += d[bb] * d[bb];
    ss += __shfl_xor_sync(0xFFFFFFFFu, ss, 1);

    const float rn  = 1.f / fmaxf(sqrtf(ss), 1e-12f);
    const float aij = a[ij];

#pragma unroll
    for (int bb = 0; bb < 16; bb++) {
        float v = __expf(fmaxf((1.f - d[bb] * rn) * aij, 0.f));
        g_tmpS[(b0 + bb) * CC_ + ij] = v;
    }
}

// ---------------------------------------------------------------------------
// Kernel C: y[b,j,l] = (1/cs[b,j]) * sum_i tmpS[b,i,j] * x[b,i,l]
// Column sums in-kernel; epilogue writes bf16 hi/lo words into g_Ah/g_Al
// (words 128..255 of row b*128+j). grid (4 l, 4 j, 32 b), 128 threads.
// ---------------------------------------------------------------------------
__global__ void k_y(const float* __restrict__ x) {
    __shared__ float sS[16][32];
    __shared__ float sX[16][64];
    __shared__ float srcs[32];
    const int b  = blockIdx.z;
    const int j0 = blockIdx.y * 32;
    const int lBase = blockIdx.x * 64;
    const int tid = threadIdx.x;
    const int tx = tid & 15, ty = tid >> 4;  // ty 0..7

    float acc[4][4];
#pragma unroll
    for (int r = 0; r < 4; r++)
#pragma unroll
        for (int c = 0; c < 4; c++) acc[r][c] = 0.f;
    float csum = 0.f;

    const float* Sb = g_tmpS + b * CC_;
    const float* Xb = x + b * C_ * L_;

#pragma unroll 1
    for (int i0 = 0; i0 < C_; i0 += 16) {
        __syncthreads();
#pragma unroll
        for (int rep = 0; rep < 4; rep++) {
            int idx = rep * 128 + tid;
            int r = idx >> 5, c = idx & 31;
            sS[r][c] = Sb[(i0 + r) * C_ + j0 + c];
        }
#pragma unroll
        for (int rep = 0; rep < 8; rep++) {
            int idx = rep * 128 + tid;
            int r = idx >> 6, c = idx & 63;
            sX[r][c] = Xb[(i0 + r) * L_ + lBase + c];
        }
        __syncthreads();
        if (tid < 32) {
#pragma unroll
            for (int r = 0; r < 16; r++) csum += sS[r][tid];
        }
#pragma unroll
        for (int i = 0; i < 16; i++) {
            float4 av = *reinterpret_cast<const float4*>(&sS[i][ty * 4]);
            float4 bv = *reinterpret_cast<const float4*>(&sX[i][tx * 4]);
            float a4[4] = {av.x, av.y, av.z, av.w};
            float b4[4] = {bv.x, bv.y, bv.z, bv.w};
#pragma unroll
            for (int r = 0; r < 4; r++)
#pragma unroll
                for (int c = 0; c < 4; c++)
                    acc[r][c] += a4[r] * b4[c];
        }
    }
    if (tid < 32) srcs[tid] = 1.f / csum;
    __syncthreads();

#pragma unroll
    for (int r = 0; r < 4; r++) {
        int jj = j0 + ty * 4 + r;
        float rc = srcs[ty * 4 + r];
        float vx = acc[r][0] * rc, vy = acc[r][1] * rc;
        float vz = acc[r][2] * rc, vw = acc[r][3] * rc;
        uint32_t h0, l0v, h1, l1v;
        bf16_split2(vx, vy, h0, l0v);
        bf16_split2(vz, vw, h1, l1v);
        size_t o = (size_t)(b * 128 + jj) * 256 + 128 + (lBase >> 1) + tx * 2;
        *reinterpret_cast<uint2*>(&g_Ah[o]) = make_uint2(h0, h1);
        *reinterpret_cast<uint2*>(&g_Al[o]) = make_uint2(l0v, l1v);
    }
}

// ---------------------------------------------------------------------------
// Kernel D (bf16 m16n8k16 MMA, 3-product split, precomputed operands,
// ldmatrix, cp.async 3-STAGE pipeline with wait_group 1):
//   out = relu(A @ B^T), M=4096, N=256, K=512.
// CTA 64x64, 128 threads (4 warps 2x2, warp tile 32x32). grid (4 n, 64 m).
// Each slab's copy is issued 2 slabs ahead -> ~2 slabs of MMA work cover the
// global-load latency. Dynamic smem: 3 stages x 20 KB = 60 KB.
// ---------------------------------------------------------------------------
#define STG_B   (64 * 20 * 4)      // 5120 bytes per array
#define STAGE_B (4 * STG_B)        // 20480 bytes per stage
#define KOUT_SMEM (3 * STAGE_B)    // 61440

__global__ void __launch_bounds__(128) k_out_mma(float* __restrict__ out) {
    extern __shared__ uint32_t sm[];

    const int tid  = threadIdx.x;
    const int lane = tid & 31, wid = tid >> 5;
    const int n0 = blockIdx.x * 64;
    const int r0 = blockIdx.y * 64;
    const int wm = (wid >> 1) * 32;
    const int wn = (wid & 1) * 32;
    const int qr = lane >> 2, qc = lane & 3;

    const uint32_t smbase = (uint32_t)__cvta_generic_to_shared(sm);

    // ldmatrix per-lane offsets (bytes within a stage)
    const int tq = lane >> 3, e = lane & 7;
    const uint32_t aoff = ((uint32_t)((wm + ((tq & 1) << 3) + e) * 20
                                      + ((tq >> 1) << 2))) << 2;
    const uint32_t boff = ((uint32_t)((wn + ((tq >> 1) << 3) + e) * 20
                                      + ((tq & 1) << 2))) << 2;
    const uint32_t adH0 = smbase + 0 * STG_B + aoff;
    const uint32_t adH1 = adH0 + 1280;                 // +16 rows
    const uint32_t adL0 = smbase + 1 * STG_B + aoff;
    const uint32_t adL1 = adL0 + 1280;
    const uint32_t bdH0 = smbase + 2 * STG_B + boff;
    const uint32_t bdH1 = bdH0 + 1280;
    const uint32_t bdL0 = smbase + 3 * STG_B + boff;
    const uint32_t bdL1 = bdL0 + 1280;

    // fill coords: 128 threads x 2 reps cover 64 rows x 16 words per array
    const int frow = tid >> 2;              // 0..31 (rep adds 32)
    const int fwq  = (tid & 3) * 4;         // word offset 0,4,8,12
    const uint32_t foff0 = smbase + (uint32_t)((frow * 20 + fwq) << 2);
    const uint32_t foff1 = smbase + (uint32_t)(((frow + 32) * 20 + fwq) << 2);

    auto issue_slab = [&](int slab, uint32_t stg) {
        const uint32_t sb = stg * STAGE_B;
        const int w0 = slab * 16 + fwq;
        cpa16(sb + foff0 + 0 * STG_B, &g_Ah[(size_t)(r0 + frow) * 256 + w0]);
        cpa16(sb + foff1 + 0 * STG_B, &g_Ah[(size_t)(r0 + frow + 32) * 256 + w0]);
        cpa16(sb + foff0 + 1 * STG_B, &g_Al[(size_t)(r0 + frow) * 256 + w0]);
        cpa16(sb + foff1 + 1 * STG_B, &g_Al[(size_t)(r0 + frow + 32) * 256 + w0]);
        cpa16(sb + foff0 + 2 * STG_B, &g_Bh[(size_t)(n0 + frow) * 256 + w0]);
        cpa16(sb + foff1 + 2 * STG_B, &g_Bh[(size_t)(n0 + frow + 32) * 256 + w0]);
        cpa16(sb + foff0 + 3 * STG_B, &g_Bl[(size_t)(n0 + frow) * 256 + w0]);
        cpa16(sb + foff1 + 3 * STG_B, &g_Bl[(size_t)(n0 + frow + 32) * 256 + w0]);
        cpa_commit();
    };

    float acc[2][4][4];
#pragma unroll
    for (int mi = 0; mi < 2; mi++)
#pragma unroll
        for (int ni = 0; ni < 4; ni++)
#pragma unroll
            for (int ee = 0; ee < 4; ee++) acc[mi][ni][ee] = 0.f;

    issue_slab(0, 0);
    issue_slab(1, 1);

    int stage = 0;
#pragma unroll 1
    for (int s = 0; s < 16; s++) {
        if (s < 15) cpa_wait1(); else cpa_wait0();   // slab s complete
        __syncthreads();

        // issue slab s+2 into stage (s+2)%3 = (s-1)%3 (consumed in iter s-1)
        if (s + 2 < 16) {
            int nst = stage + 2; if (nst >= 3) nst -= 3;
            issue_slab(s + 2, (uint32_t)nst);
        }

        const uint32_t so = (uint32_t)stage * STAGE_B;
#pragma unroll
        for (int t16 = 0; t16 < 2; t16++) {
            const uint32_t o = so + t16 * 32;   // 8 words per k16 step
            uint32_t AH0[4], AH1[4], AL0[4], AL1[4];
            uint32_t BH0[4], BH1[4], BL0[4], BL1[4];
            ldmx4(AH0, adH0 + o);  ldmx4(AH1, adH1 + o);
            ldmx4(BH0, bdH0 + o);  ldmx4(BH1, bdH1 + o);
            ldmx4(AL0, adL0 + o);  ldmx4(AL1, adL1 + o);
            ldmx4(BL0, bdL0 + o);  ldmx4(BL1, bdL1 + o);

            // pass 1: AH * BH
            mma_bf16(acc[0][0], AH0, &BH0[0]);  mma_bf16(acc[0][1], AH0, &BH0[2]);
            mma_bf16(acc[0][2], AH0, &BH1[0]);  mma_bf16(acc[0][3], AH0, &BH1[2]);
            mma_bf16(acc[1][0], AH1, &BH0[0]);  mma_bf16(acc[1][1], AH1, &BH0[2]);
            mma_bf16(acc[1][2], AH1, &BH1[0]);  mma_bf16(acc[1][3], AH1, &BH1[2]);
            // pass 2: AL * BH
            mma_bf16(acc[0][0], AL0, &BH0[0]);  mma_bf16(acc[0][1], AL0, &BH0[2]);
            mma_bf16(acc[0][2], AL0, &BH1[0]);  mma_bf16(acc[0][3], AL0, &BH1[2]);
            mma_bf16(acc[1][0], AL1, &BH0[0]);  mma_bf16(acc[1][1], AL1, &BH0[2]);
            mma_bf16(acc[1][2], AL1, &BH1[0]);  mma_bf16(acc[1][3], AL1, &BH1[2]);
            // pass 3: AH * BL
            mma_bf16(acc[0][0], AH0, &BL0[0]);  mma_bf16(acc[0][1], AH0, &BL0[2]);
            mma_bf16(acc[0][2], AH0, &BL1[0]);  mma_bf16(acc[0][3], AH0, &BL1[2]);
            mma_bf16(acc[1][0], AH1, &BL0[0]);  mma_bf16(acc[1][1], AH1, &BL0[2]);
            mma_bf16(acc[1][2], AH1, &BL1[0]);  mma_bf16(acc[1][3], AH1, &BL1[2]);
        }
        stage++; if (stage >= 3) stage = 0;
    }

    // epilogue: relu + store
#pragma unroll
    for (int mi = 0; mi < 2; mi++) {
        int row = r0 + wm + mi * 16 + qr;
#pragma unroll
        for (int ni = 0; ni < 4; ni++) {
            int col = n0 + wn + ni * 8 + qc * 2;
            float2 v0 = make_float2(fmaxf(acc[mi][ni][0], 0.f),
                                    fmaxf(acc[mi][ni][1], 0.f));
            float2 v1 = make_float2(fmaxf(acc[mi][ni][2], 0.f),
                                    fmaxf(acc[mi][ni][3], 0.f));
            *reinterpret_cast<float2*>(out + (size_t)row * L_ + col) = v0;
            *reinterpret_cast<float2*>(out + (size_t)(row + 8) * L_ + col) = v1;
        }
    }
}

// ---------------------------------------------------------------------------
extern "C" void kernel_launch(void* const* d_in, const int* in_sizes, int n_in,
                              void* d_out, int out_size) {
    const float* x     = (const float*)d_in[0];   // [32,128,256]
    const float* a     = (const float*)d_in[1];   // [128,128]
    const float* Theta = (const float*)d_in[2];   // [2,256,256]
    float* out = (float*)d_out;                   // [32,128,256]

    // idempotent, deterministic: set every call (not an allocation)
    cudaFuncSetAttribute(k_out_mma, cudaFuncAttributeMaxDynamicSharedMemorySize,
                         KOUT_SMEM);

    k_ttdiff <<<dim3(44, 32),   256>>>(x, Theta);
    k_nt     <<<256,            128>>>(a);
    k_y      <<<dim3(4, 4, 32), 128>>>(x);
    k_out_mma<<<dim3(4, 64),    128, KOUT_SMEM>>>(out);
}

// round 15
// speedup vs baseline: 1.1231x; 1.0432x over previous
#include <cuda_runtime.h>
#include <cuda_bf16.h>
#include <cstdint>

#define B_  32
#define C_  128
#define L_  256
#define CC_ (C_ * C_)      // 16384
#define BCC_ (B_ * CC_)    // 524288

// Scratch (device globals — no allocations allowed)
__device__ float    g_diff[BCC_];       // [b][i][j] pairwise L1
__device__ float    g_tmpS[BCC_];       // exp(relu((1-diffn)*a))
__device__ uint32_t g_Ah[4096 * 256];   // A=[x|y] bf16-hi packed x2, [row][kword]
__device__ uint32_t g_Al[4096 * 256];   // A bf16-lo residual
__device__ uint32_t g_Bh[256 * 256];    // B=(signed Theta^T) bf16-hi, [n][kword]
__device__ uint32_t g_Bl[256 * 256];    // B bf16-lo

// ===========================================================================
// helpers
// ===========================================================================
__device__ __forceinline__ void bf16_split2(float x, float y,
                                            uint32_t& hi, uint32_t& lo) {
    __nv_bfloat16 hx = __float2bfloat16(x);
    __nv_bfloat16 hy = __float2bfloat16(y);
    __nv_bfloat16 lx = __float2bfloat16(x - __bfloat162float(hx));
    __nv_bfloat16 ly = __float2bfloat16(y - __bfloat162float(hy));
    hi = (uint32_t)__bfloat16_as_ushort(hx) | ((uint32_t)__bfloat16_as_ushort(hy) << 16);
    lo = (uint32_t)__bfloat16_as_ushort(lx) | ((uint32_t)__bfloat16_as_ushort(ly) << 16);
}
__device__ __forceinline__ void mma_bf16(float c[4], const uint32_t a[4],
                                         const uint32_t b[2]) {
    asm volatile(
        "mma.sync.aligned.m16n8k16.row.col.f32.bf16.bf16.f32 "
        "{%0,%1,%2,%3}, {%4,%5,%6,%7}, {%8,%9}, {%0,%1,%2,%3};"
        : "+f"(c[0]), "+f"(c[1]), "+f"(c[2]), "+f"(c[3])
        : "r"(a[0]), "r"(a[1]), "r"(a[2]), "r"(a[3]), "r"(b[0]), "r"(b[1]));
}
__device__ __forceinline__ void ldmx4(uint32_t r[4], uint32_t addr) {
    asm volatile(
        "ldmatrix.sync.aligned.m8n8.x4.shared.b16 {%0,%1,%2,%3}, [%4];"
        : "=r"(r[0]), "=r"(r[1]), "=r"(r[2]), "=r"(r[3]) : "r"(addr));
}
__device__ __forceinline__ void cpa16(uint32_t smem_addr, const void* gptr) {
    asm volatile("cp.async.ca.shared.global [%0], [%1], 16;"
                 :: "r"(smem_addr), "l"(gptr) : "memory");
}
__device__ __forceinline__ void cpa_commit() {
    asm volatile("cp.async.commit_group;" ::: "memory");
}
__device__ __forceinline__ void cpa_wait1() {
    asm volatile("cp.async.wait_group 1;" ::: "memory");
}

// ---------------------------------------------------------------------------
// Kernel A (merged): bx<36: symmetric pairwise-L1 diff; 36..39: Theta ->
// bf16 hi/lo B operand; 40..43: x -> bf16 hi/lo A operand (k<256).
// grid (44, 32), 256 threads.
// ---------------------------------------------------------------------------
__global__ void __launch_bounds__(256) k_ttdiff(const float* __restrict__ x,
                                                const float* __restrict__ Theta) {
    __shared__ float sxi[16][260];
    __shared__ float sxj[16][260];
    const int tid = threadIdx.x;

    if (blockIdx.x >= 40) {
        // ---- x -> g_Ah/g_Al (words 0..127 of each row) ----
        const int id = (blockIdx.x - 40) * 32 + blockIdx.y;   // 0..127
#pragma unroll
        for (int it = 0; it < 8; it++) {
            int idx = id * 2048 + it * 256 + tid;             // 0..262143 float4s
            int row = idx >> 6, f4 = idx & 63;
            float4 v = *reinterpret_cast<const float4*>(x + (size_t)row * 256 + f4 * 4);
            uint32_t h0, l0v, h1, l1v;
            bf16_split2(v.x, v.y, h0, l0v);
            bf16_split2(v.z, v.w, h1, l1v);
            *reinterpret_cast<uint2*>(&g_Ah[(size_t)row * 256 + f4 * 2]) = make_uint2(h0, h1);
            *reinterpret_cast<uint2*>(&g_Al[(size_t)row * 256 + f4 * 2]) = make_uint2(l0v, l1v);
        }
        return;
    }

    if (blockIdx.x >= 36) {
        // ---- Theta transpose/sign-fold -> g_Bh/g_Bl ----
        __shared__ float t[32][33];
        const int id = (blockIdx.x - 36) * 32 + blockIdx.y;   // 0..127
        const int kt = (id >> 3) * 32, nt = (id & 7) * 32;
        const int tx = tid & 31, ty = tid >> 5;               // ty 0..7
#pragma unroll
        for (int r = 0; r < 32; r += 8) {
            int k = kt + ty + r;
            int n = nt + tx;
            float v = (k < 256) ? Theta[k * 256 + n]
                                : -Theta[65536 + (k - 256) * 256 + n];
            t[ty + r][tx] = v;                                 // t[k_local][n_local]
        }
        __syncthreads();
        const int nl = tid >> 3, wl8 = tid & 7;
#pragma unroll
        for (int rep = 0; rep < 2; rep++) {
            int wl = wl8 + rep * 8;                            // word 0..15
            uint32_t hv, lv;
            bf16_split2(t[2 * wl][nl], t[2 * wl + 1][nl], hv, lv);
            size_t o = (size_t)(nt + nl) * 256 + (kt >> 1) + wl;
            g_Bh[o] = hv;
            g_Bl[o] = lv;
        }
        return;
    }

    // ---- diff part: tile-pair (ti<=tj) of 16x16, mirror-write ----
    const int b = blockIdx.y;
    int rem = blockIdx.x, ti = 0;
    while (rem >= 8 - ti) { rem -= 8 - ti; ti++; }
    const int tj = ti + rem;
    const int i0 = ti * 16, j0 = tj * 16;
    const float* xb = x + b * C_ * L_;

#pragma unroll
    for (int rep = 0; rep < 4; rep++) {
        int idx = rep * 256 + tid;
        int row = idx >> 6, c4 = (idx & 63) * 4;
        *reinterpret_cast<float4*>(&sxi[row][c4]) =
            *reinterpret_cast<const float4*>(xb + (i0 + row) * L_ + c4);
        *reinterpret_cast<float4*>(&sxj[row][c4]) =
            *reinterpret_cast<const float4*>(xb + (j0 + row) * L_ + c4);
    }
    __syncthreads();

    const int ii = tid >> 4, jj = tid & 15;
    const float* ri = &sxi[ii][0];
    const float* rj = &sxj[jj][0];

    float a0 = 0.f, a1 = 0.f, a2 = 0.f, a3 = 0.f;
#pragma unroll
    for (int l = 0; l < L_; l += 16) {
        float4 u0 = *reinterpret_cast<const float4*>(ri + l);
        float4 v0 = *reinterpret_cast<const float4*>(rj + l);
        float4 u1 = *reinterpret_cast<const float4*>(ri + l + 4);
        float4 v1 = *reinterpret_cast<const float4*>(rj + l + 4);
        float4 u2 = *reinterpret_cast<const float4*>(ri + l + 8);
        float4 v2 = *reinterpret_cast<const float4*>(rj + l + 8);
        float4 u3 = *reinterpret_cast<const float4*>(ri + l + 12);
        float4 v3 = *reinterpret_cast<const float4*>(rj + l + 12);
        a0 += fabsf(u0.x - v0.x) + fabsf(u0.y - v0.y)
            + fabsf(u0.z - v0.z) + fabsf(u0.w - v0.w);
        a1 += fabsf(u1.x - v1.x) + fabsf(u1.y - v1.y)
            + fabsf(u1.z - v1.z) + fabsf(u1.w - v1.w);
        a2 += fabsf(u2.x - v2.x) + fabsf(u2.y - v2.y)
            + fabsf(u2.z - v2.z) + fabsf(u2.w - v2.w);
        a3 += fabsf(u3.x - v3.x) + fabsf(u3.y - v3.y)
            + fabsf(u3.z - v3.z) + fabsf(u3.w - v3.w);
    }
    float res = (a0 + a1) + (a2 + a3);

    g_diff[b * CC_ + (i0 + ii) * C_ + (j0 + jj)] = res;
    if (ti != tj)
        g_diff[b * CC_ + (j0 + jj) * C_ + (i0 + ii)] = res;
}

// ---------------------------------------------------------------------------
// Kernel B (fused norm+tmps): 2 threads per (i,j), b split 16/16, shfl combine.
// ---------------------------------------------------------------------------
__global__ void __launch_bounds__(128) k_nt(const float* __restrict__ a) {
    const int g  = blockIdx.x * 128 + threadIdx.x;
    const int ij = g >> 1;
    const int b0 = (g & 1) * 16;

    float d[16];
#pragma unroll
    for (int bb = 0; bb < 16; bb++) d[bb] = g_diff[(b0 + bb) * CC_ + ij];

    float ss = 0.f;
#pragma unroll
    for (int bb = 0; bb < 16; bb++) ss += d[bb] * d[bb];
    ss += __shfl_xor_sync(0xFFFFFFFFu, ss, 1);

    const float rn  = 1.f / fmaxf(sqrtf(ss), 1e-12f);
    const float aij = a[ij];

#pragma unroll
    for (int bb = 0; bb < 16; bb++) {
        float v = __expf(fmaxf((1.f - d[bb] * rn) * aij, 0.f));
        g_tmpS[(b0 + bb) * CC_ + ij] = v;
    }
}

// ---------------------------------------------------------------------------
// Kernel C: y[b,j,l] = (1/cs[b,j]) * sum_i tmpS[b,i,j] * x[b,i,l]
// Column sums in-kernel; epilogue writes bf16 hi/lo words into g_Ah/g_Al
// (words 128..255 of row b*128+j). grid (4 l, 4 j, 32 b), 128 threads.
// ---------------------------------------------------------------------------
__global__ void k_y(const float* __restrict__ x) {
    __shared__ float sS[16][32];
    __shared__ float sX[16][64];
    __shared__ float srcs[32];
    const int b  = blockIdx.z;
    const int j0 = blockIdx.y * 32;
    const int lBase = blockIdx.x * 64;
    const int tid = threadIdx.x;
    const int tx = tid & 15, ty = tid >> 4;  // ty 0..7

    float acc[4][4];
#pragma unroll
    for (int r = 0; r < 4; r++)
#pragma unroll
        for (int c = 0; c < 4; c++) acc[r][c] = 0.f;
    float csum = 0.f;

    const float* Sb = g_tmpS + b * CC_;
    const float* Xb = x + b * C_ * L_;

#pragma unroll 1
    for (int i0 = 0; i0 < C_; i0 += 16) {
        __syncthreads();
#pragma unroll
        for (int rep = 0; rep < 4; rep++) {
            int idx = rep * 128 + tid;
            int r = idx >> 5, c = idx & 31;
            sS[r][c] = Sb[(i0 + r) * C_ + j0 + c];
        }
#pragma unroll
        for (int rep = 0; rep < 8; rep++) {
            int idx = rep * 128 + tid;
            int r = idx >> 6, c = idx & 63;
            sX[r][c] = Xb[(i0 + r) * L_ + lBase + c];
        }
        __syncthreads();
        if (tid < 32) {
#pragma unroll
            for (int r = 0; r < 16; r++) csum += sS[r][tid];
        }
#pragma unroll
        for (int i = 0; i < 16; i++) {
            float4 av = *reinterpret_cast<const float4*>(&sS[i][ty * 4]);
            float4 bv = *reinterpret_cast<const float4*>(&sX[i][tx * 4]);
            float a4[4] = {av.x, av.y, av.z, av.w};
            float b4[4] = {bv.x, bv.y, bv.z, bv.w};
#pragma unroll
            for (int r = 0; r < 4; r++)
#pragma unroll
                for (int c = 0; c < 4; c++)
                    acc[r][c] += a4[r] * b4[c];
        }
    }
    if (tid < 32) srcs[tid] = 1.f / csum;
    __syncthreads();

#pragma unroll
    for (int r = 0; r < 4; r++) {
        int jj = j0 + ty * 4 + r;
        float rc = srcs[ty * 4 + r];
        float vx = acc[r][0] * rc, vy = acc[r][1] * rc;
        float vz = acc[r][2] * rc, vw = acc[r][3] * rc;
        uint32_t h0, l0v, h1, l1v;
        bf16_split2(vx, vy, h0, l0v);
        bf16_split2(vz, vw, h1, l1v);
        size_t o = (size_t)(b * 128 + jj) * 256 + 128 + (lBase >> 1) + tx * 2;
        *reinterpret_cast<uint2*>(&g_Ah[o]) = make_uint2(h0, h1);
        *reinterpret_cast<uint2*>(&g_Al[o]) = make_uint2(l0v, l1v);
    }
}

// ---------------------------------------------------------------------------
// Kernel D (bf16 m16n8k16 MMA, 3-product split, precomputed operands,
// ldmatrix, 3-stage cp.async pipeline, FRAGMENT DOUBLE-BUFFERING):
//   out = relu(A @ B^T), M=4096, N=256, K=512.
// CTA 64x64, 128 threads (4 warps 2x2, warp tile 32x32). grid (4 n, 64 m).
// Each k16-step's fragments are ldmatrix'd one phase ahead, so the LDSM
// latency hides behind the previous step's 24 MMAs.
// ---------------------------------------------------------------------------
#define STG_B   (64 * 20 * 4)      // 5120 bytes per array
#define STAGE_B (4 * STG_B)        // 20480 bytes per stage
#define KOUT_SMEM (3 * STAGE_B)    // 61440

__global__ void __launch_bounds__(128) k_out_mma(float* __restrict__ out) {
    extern __shared__ uint32_t sm[];

    const int tid  = threadIdx.x;
    const int lane = tid & 31, wid = tid >> 5;
    const int n0 = blockIdx.x * 64;
    const int r0 = blockIdx.y * 64;
    const int wm = (wid >> 1) * 32;
    const int wn = (wid & 1) * 32;
    const int qr = lane >> 2, qc = lane & 3;

    const uint32_t smbase = (uint32_t)__cvta_generic_to_shared(sm);

    // ldmatrix per-lane offsets (bytes within a stage)
    const int tq = lane >> 3, e = lane & 7;
    const uint32_t aoff = ((uint32_t)((wm + ((tq & 1) << 3) + e) * 20
                                      + ((tq >> 1) << 2))) << 2;
    const uint32_t boff = ((uint32_t)((wn + ((tq >> 1) << 3) + e) * 20
                                      + ((tq & 1) << 2))) << 2;
    const uint32_t adH0 = smbase + 0 * STG_B + aoff;
    const uint32_t adH1 = adH0 + 1280;                 // +16 rows
    const uint32_t adL0 = smbase + 1 * STG_B + aoff;
    const uint32_t adL1 = adL0 + 1280;
    const uint32_t bdH0 = smbase + 2 * STG_B + boff;
    const uint32_t bdH1 = bdH0 + 1280;
    const uint32_t bdL0 = smbase + 3 * STG_B + boff;
    const uint32_t bdL1 = bdL0 + 1280;

    // fill coords: 128 threads x 2 reps cover 64 rows x 16 words per array
    const int frow = tid >> 2;              // 0..31 (rep adds 32)
    const int fwq  = (tid & 3) * 4;         // word offset 0,4,8,12
    const uint32_t foff0 = smbase + (uint32_t)((frow * 20 + fwq) << 2);
    const uint32_t foff1 = smbase + (uint32_t)(((frow + 32) * 20 + fwq) << 2);

    auto issue_slab = [&](int slab, uint32_t stg) {
        const uint32_t sb = stg * STAGE_B;
        const int w0 = slab * 16 + fwq;
        cpa16(sb + foff0 + 0 * STG_B, &g_Ah[(size_t)(r0 + frow) * 256 + w0]);
        cpa16(sb + foff1 + 0 * STG_B, &g_Ah[(size_t)(r0 + frow + 32) * 256 + w0]);
        cpa16(sb + foff0 + 1 * STG_B, &g_Al[(size_t)(r0 + frow) * 256 + w0]);
        cpa16(sb + foff1 + 1 * STG_B, &g_Al[(size_t)(r0 + frow + 32) * 256 + w0]);
        cpa16(sb + foff0 + 2 * STG_B, &g_Bh[(size_t)(n0 + frow) * 256 + w0]);
        cpa16(sb + foff1 + 2 * STG_B, &g_Bh[(size_t)(n0 + frow + 32) * 256 + w0]);
        cpa16(sb + foff0 + 3 * STG_B, &g_Bl[(size_t)(n0 + frow) * 256 + w0]);
        cpa16(sb + foff1 + 3 * STG_B, &g_Bl[(size_t)(n0 + frow + 32) * 256 + w0]);
        cpa_commit();
    };

    // fragment buffers: [buf][AH0,AH1,AL0,AL1][4] / [buf][BH0,BH1,BL0,BL1][4]
    uint32_t fA[2][4][4], fB[2][4][4];
    auto load_frags = [&](int buf, uint32_t o) {
        ldmx4(fA[buf][0], adH0 + o);  ldmx4(fA[buf][1], adH1 + o);
        ldmx4(fB[buf][0], bdH0 + o);  ldmx4(fB[buf][1], bdH1 + o);
        ldmx4(fA[buf][2], adL0 + o);  ldmx4(fA[buf][3], adL1 + o);
        ldmx4(fB[buf][2], bdL0 + o);  ldmx4(fB[buf][3], bdL1 + o);
    };

    float acc[2][4][4];
#pragma unroll
    for (int mi = 0; mi < 2; mi++)
#pragma unroll
        for (int ni = 0; ni < 4; ni++)
#pragma unroll
            for (int ee = 0; ee < 4; ee++) acc[mi][ni][ee] = 0.f;

    auto mma_all = [&](int buf) {
        // pass 1: AH * BH
        mma_bf16(acc[0][0], fA[buf][0], &fB[buf][0][0]);
        mma_bf16(acc[0][1], fA[buf][0], &fB[buf][0][2]);
        mma_bf16(acc[0][2], fA[buf][0], &fB[buf][1][0]);
        mma_bf16(acc[0][3], fA[buf][0], &fB[buf][1][2]);
        mma_bf16(acc[1][0], fA[buf][1], &fB[buf][0][0]);
        mma_bf16(acc[1][1], fA[buf][1], &fB[buf][0][2]);
        mma_bf16(acc[1][2], fA[buf][1], &fB[buf][1][0]);
        mma_bf16(acc[1][3], fA[buf][1], &fB[buf][1][2]);
        // pass 2: AL * BH
        mma_bf16(acc[0][0], fA[buf][2], &fB[buf][0][0]);
        mma_bf16(acc[0][1], fA[buf][2], &fB[buf][0][2]);
        mma_bf16(acc[0][2], fA[buf][2], &fB[buf][1][0]);
        mma_bf16(acc[0][3], fA[buf][2], &fB[buf][1][2]);
        mma_bf16(acc[1][0], fA[buf][3], &fB[buf][0][0]);
        mma_bf16(acc[1][1], fA[buf][3], &fB[buf][0][2]);
        mma_bf16(acc[1][2], fA[buf][3], &fB[buf][1][0]);
        mma_bf16(acc[1][3], fA[buf][3], &fB[buf][1][2]);
        // pass 3: AH * BL
        mma_bf16(acc[0][0], fA[buf][0], &fB[buf][2][0]);
        mma_bf16(acc[0][1], fA[buf][0], &fB[buf][2][2]);
        mma_bf16(acc[0][2], fA[buf][0], &fB[buf][3][0]);
        mma_bf16(acc[0][3], fA[buf][0], &fB[buf][3][2]);
        mma_bf16(acc[1][0], fA[buf][1], &fB[buf][2][0]);
        mma_bf16(acc[1][1], fA[buf][1], &fB[buf][2][2]);
        mma_bf16(acc[1][2], fA[buf][1], &fB[buf][3][0]);
        mma_bf16(acc[1][3], fA[buf][1], &fB[buf][3][2]);
    };

    issue_slab(0, 0);
    issue_slab(1, 1);

    cpa_wait1();            // slab 0 resident
    __syncthreads();
    load_frags(0, 0u);      // k16-step 0 of slab 0 (stage 0)

    int stage = 0;
#pragma unroll 1
    for (int s = 0; s < 16; s++) {
        const uint32_t so = (uint32_t)stage * STAGE_B;
        // load second k16-step of current slab, then run step 0's MMAs
        load_frags(1, so + 32);
        mma_all(0);

        // issue slab s+2 into stage (s+2)%3 (its last reads ended pre-sync(s-1))
        if (s + 2 < 16) {
            int nst = stage + 2; if (nst >= 3) nst -= 3;
            issue_slab(s + 2, (uint32_t)nst);
        }

        int nstage = stage + 1; if (nstage >= 3) nstage = 0;
        if (s < 15) {
            cpa_wait1();        // slab s+1 resident (s+2 may be in flight)
            __syncthreads();
            load_frags(0, (uint32_t)nstage * STAGE_B);  // step 0 of slab s+1
        }
        // step 1's MMAs (fragments already in registers)
        mma_all(1);
        stage = nstage;
    }

    // epilogue: relu + store
#pragma unroll
    for (int mi = 0; mi < 2; mi++) {
        int row = r0 + wm + mi * 16 + qr;
#pragma unroll
        for (int ni = 0; ni < 4; ni++) {
            int col = n0 + wn + ni * 8 + qc * 2;
            float2 v0 = make_float2(fmaxf(acc[mi][ni][0], 0.f),
                                    fmaxf(acc[mi][ni][1], 0.f));
            float2 v1 = make_float2(fmaxf(acc[mi][ni][2], 0.f),
                                    fmaxf(acc[mi][ni][3], 0.f));
            *reinterpret_cast<float2*>(out + (size_t)row * L_ + col) = v0;
            *reinterpret_cast<float2*>(out + (size_t)(row + 8) * L_ + col) = v1;
        }
    }
}

// ---------------------------------------------------------------------------
extern "C" void kernel_launch(void* const* d_in, const int* in_sizes, int n_in,
                              void* d_out, int out_size) {
    const float* x     = (const float*)d_in[0];   // [32,128,256]
    const float* a     = (const float*)d_in[1];   // [128,128]
    const float* Theta = (const float*)d_in[2];   // [2,256,256]
    float* out = (float*)d_out;                   // [32,128,256]

    // idempotent, deterministic: set every call (not an allocation)
    cudaFuncSetAttribute(k_out_mma, cudaFuncAttributeMaxDynamicSharedMemorySize,
                         KOUT_SMEM);

    k_ttdiff <<<dim3(44, 32),   256>>>(x, Theta);
    k_nt     <<<256,            128>>>(a);
    k_y      <<<dim3(4, 4, 32), 128>>>(x);
    k_out_mma<<<dim3(4, 64),    128, KOUT_SMEM>>>(out);
}